// round 11
// baseline (speedup 1.0000x reference)
#include <cuda_runtime.h>
#include <cstdint>
#include <climits>

// ---------------- problem constants (match reference exactly) ----------------
#define BB   4
#define NPTS 300000
#define NC   5
#define GXX  432
#define GYY  496
#define GZZ  1
#define NVOX (GXX * GYY * GZZ)          // 214272 (divisible by 4)
#define MAXV 40000
#define MAXP 30
#define CAP  48                          // per-voxel index bucket capacity
#define CHUNK 4096
#define NB   ((NVOX + CHUNK - 1) / CHUNK)   // 53

#define FEATS_ELEMS ((size_t)BB * MAXV * MAXP * NC)   // 24,000,000 floats
#define F4_FEATS (24000000 / 4)
#define F4_COORD ((BB * MAXV * 4) / 4)   // 160,000 float4

#define I4_CNT   ((BB * NVOX) / 4)
#define I4_AGG   ((BB * NB + 3) / 4)
#define I4_VL    ((BB * MAXV) / 4)
#define FILL_TOTAL (I4_CNT + I4_AGG + I4_VL + F4_COORD)

#define VALIDF (1 << 30)
#define ROWF   (MAXP * NC)               // 150 floats per feats row
#define RPB    32                         // rows per k_out block
#define NBLK_OUT ((BB * MAXV) / RPB)      // 5000

// ---------------- static device scratch (16B-aligned for vector ops) ----------
__device__ int4 g_count4[(BB * NVOX) / 4];
__device__ int4 g_agg4  [I4_AGG];
__device__ int4 g_vlist4[I4_VL];         // row -> vid (or -1)
__device__ int  g_bucket[(size_t)BB * NVOX * CAP];

#define G_COUNT ((int*)g_count4)
#define G_AGG   ((int*)g_agg4)
#define G_VLIST ((int*)g_vlist4)

// ---------------- init: counts=0, agg=0, vlist=-1, coords=-1 -------------------
__global__ void k_fill(float4* __restrict__ out4) {
    int i = blockIdx.x * blockDim.x + threadIdx.x;
    if (i < I4_CNT) { g_count4[i] = make_int4(0, 0, 0, 0); return; }
    i -= I4_CNT;
    if (i < I4_AGG) { g_agg4[i] = make_int4(0, 0, 0, 0); return; }
    i -= I4_AGG;
    if (i < I4_VL)  { g_vlist4[i] = make_int4(-1, -1, -1, -1); return; }
    i -= I4_VL;
    if (i < F4_COORD) out4[F4_FEATS + i] = make_float4(-1.f, -1.f, -1.f, -1.f);
}

// ---------------- pass 1: voxelize + bucket append (no zeroing) ----------------
__global__ void k_points(const float* __restrict__ pts) {
    int tid = blockIdx.x * blockDim.x + threadIdx.x;
    if (tid >= BB * NPTS) return;
    int b = tid / NPTS;
    int n = tid - b * NPTS;
    const float* p = pts + (size_t)tid * NC;
    float x = __ldg(p + 0), y = __ldg(p + 1), z = __ldg(p + 2);
    // identical float32 ops as reference: floor((p - lo) / vs)
    int ix = (int)floorf((x - 0.0f)   / 0.16f);
    int iy = (int)floorf((y + 39.68f) / 0.16f);
    int iz = (int)floorf((z + 3.0f)   / 4.0f);
    if (ix < 0 || ix >= GXX || iy < 0 || iy >= GYY || iz < 0 || iz >= GZZ) return;
    int vid = (iz * GYY + iy) * GXX + ix;
    int cell = b * NVOX + vid;
    int pos = atomicAdd(&G_COUNT[cell], 1);
    if (pos < CAP) g_bucket[(size_t)cell * CAP + pos] = n;
}

// ---------------- single-pass scan with decoupled lookback --------------------
// 212 blocks (256 thr, 16 cells/thread) fit in one wave -> spin-wait is safe.
// Writes vlist[row]=vid AND the coords rows (coords = f(vid, rank)).
__global__ void k_scan(float* __restrict__ out) {
    int blk = blockIdx.x;
    int b  = blk / NB;
    int cb = blk - b * NB;
    int t  = threadIdx.x;
    __shared__ int sh[256];

    int base = cb * CHUNK + t * 16;
    int f[16];
    int s = 0;
    #pragma unroll
    for (int q = 0; q < 16; q += 4) {
        if (base + q < NVOX) {
            int4 c4 = __ldg((const int4*)(G_COUNT + b * NVOX + base + q));
            f[q + 0] = (c4.x > 0);
            f[q + 1] = (c4.y > 0);
            f[q + 2] = (c4.z > 0);
            f[q + 3] = (c4.w > 0);
        } else {
            f[q + 0] = f[q + 1] = f[q + 2] = f[q + 3] = 0;
        }
        s += f[q + 0] + f[q + 1] + f[q + 2] + f[q + 3];
    }
    sh[t] = s;
    __syncthreads();
    #pragma unroll
    for (int off = 1; off < 256; off <<= 1) {   // Hillis–Steele inclusive
        int v = (t >= off) ? sh[t - off] : 0;
        __syncthreads();
        sh[t] += v;
        __syncthreads();
    }
    int excl  = sh[t] - s;
    int total = sh[255];

    if (t == 0) atomicExch(&G_AGG[blk], total | VALIDF);

    int partial = 0;
    for (int j = t; j < cb; j += 256) {
        int v;
        do { v = atomicAdd(&G_AGG[b * NB + j], 0); } while (!(v & VALIDF));
        partial += (v & (VALIDF - 1));
    }
    __syncthreads();
    sh[t] = partial;
    __syncthreads();
    #pragma unroll
    for (int off = 128; off > 0; off >>= 1) {
        if (t < off) sh[t] += sh[t + off];
        __syncthreads();
    }
    int r = sh[0] + excl;

    float4* coords = (float4*)(out + FEATS_ELEMS);
    int* vl = G_VLIST + b * MAXV;
    #pragma unroll
    for (int q = 0; q < 16; q++) {
        if (f[q]) {
            int vid = base + q;
            if (r < MAXV) {
                vl[r] = vid;
                int izc = vid / (GXX * GYY);
                int rem = vid - izc * (GXX * GYY);
                coords[b * MAXV + r] = make_float4((float)b, (float)izc,
                                                   (float)(rem / GXX),
                                                   (float)(rem % GXX));
            }
            r++;
        }
    }
}

// ---------------- fused output: 32 rows per block, feats written ONCE ----------
// Stage 32 rows (19200B) in smem: zero, gather real points (8 warps x 4 rows),
// then flush with 1200 fully-coalesced float4 stores.
__global__ __launch_bounds__(256) void k_out(const float* __restrict__ pts,
                                             float* __restrict__ out) {
    __shared__ float srow[RPB * ROWF];    // 19200 B
    int r0   = blockIdx.x * RPB;
    int t    = threadIdx.x;
    int lane = t & 31;
    int w    = t >> 5;                    // 8 warps

    // zero the staging buffer
    float4* s4 = (float4*)srow;
    #pragma unroll
    for (int i = t; i < RPB * ROWF / 4; i += 256)
        s4[i] = make_float4(0.f, 0.f, 0.f, 0.f);
    __syncthreads();

    // gather: warp w handles rows r0 + 4w .. r0 + 4w + 3
    #pragma unroll
    for (int k = 0; k < 4; k++) {
        int row = r0 + w * 4 + k;
        int b   = row / MAXV;
        int vid = __ldg(&G_VLIST[row]);
        if (vid < 0) continue;            // row stays zero
        int cell = b * NVOX + vid;
        int cnt  = __ldg(&G_COUNT[cell]); // same addr all lanes -> broadcast
        int m    = cnt < CAP ? cnt : CAP;
        const int* bk = g_bucket + (size_t)cell * CAP;

        int v0 = (lane < m) ? __ldg(bk + lane) : INT_MAX;
        int rk = 0;
        if (m <= 32) {                    // common path (avg m ~ 1.9)
            for (int j = 0; j < m; j++) {
                int vj = __shfl_sync(0xffffffffu, v0, j);
                rk += (vj < v0);
            }
        } else {                          // rare (P ~ 0): up to CAP entries
            int v1 = (lane + 32 < m) ? __ldg(bk + lane + 32) : INT_MAX;
            int rk1 = 0;
            for (int j = 0; j < m; j++) {
                int vj = (j < 32) ? __shfl_sync(0xffffffffu, v0, j)
                                  : __shfl_sync(0xffffffffu, v1, j - 32);
                rk  += (vj < v0);
                rk1 += (vj < v1);
            }
            if (lane + 32 < m && rk1 < MAXP) {
                const float* p = pts + ((size_t)b * NPTS + v1) * NC;
                float* sr = srow + (row - r0) * ROWF + rk1 * NC;
                sr[0] = (__ldg(p + 0) - 0.0f)   / 69.12f;
                sr[1] = (__ldg(p + 1) + 39.68f) / 79.36f;
                sr[2] = (__ldg(p + 2) + 3.0f)   / 4.0f;
                sr[3] = __ldg(p + 3);
                sr[4] = __ldg(p + 4);
            }
        }
        if (lane < m && rk < MAXP) {
            const float* p = pts + ((size_t)b * NPTS + v0) * NC;
            float* sr = srow + (row - r0) * ROWF + rk * NC;
            sr[0] = (__ldg(p + 0) - 0.0f)   / 69.12f;
            sr[1] = (__ldg(p + 1) + 39.68f) / 79.36f;
            sr[2] = (__ldg(p + 2) + 3.0f)   / 4.0f;
            sr[3] = __ldg(p + 3);
            sr[4] = __ldg(p + 4);
        }
    }
    __syncthreads();

    // flush: 19200 contiguous bytes, 16B-aligned (r0*600 % 16 == 0)
    float4* o4 = (float4*)(out + (size_t)r0 * ROWF);
    #pragma unroll
    for (int i = t; i < RPB * ROWF / 4; i += 256)
        o4[i] = s4[i];
}

// ---------------- launch ------------------------------------------------------
extern "C" void kernel_launch(void* const* d_in, const int* in_sizes, int n_in,
                              void* d_out, int out_size) {
    const float* pts = (const float*)d_in[0];
    float* out = (float*)d_out;

    k_fill  <<<(FILL_TOTAL + 255) / 256, 256>>>((float4*)out);
    k_points<<<(BB * NPTS + 255) / 256, 256>>>(pts);
    k_scan  <<<BB * NB, 256>>>(out);
    k_out   <<<NBLK_OUT, 256>>>(pts, out);
}

// round 12
// speedup vs baseline: 1.2249x; 1.2249x over previous
#include <cuda_runtime.h>
#include <cstdint>
#include <climits>

// ---------------- problem constants (match reference exactly) ----------------
#define BB   4
#define NPTS 300000
#define NC   5
#define GXX  432
#define GYY  496
#define GZZ  1
#define NVOX (GXX * GYY * GZZ)          // 214272 (divisible by 4)
#define MAXV 40000
#define MAXP 30
#define CAP  48                          // per-voxel index bucket capacity
#define CHUNK 4096
#define NB   ((NVOX + CHUNK - 1) / CHUNK)   // 53

#define FEATS_ELEMS ((size_t)BB * MAXV * MAXP * NC)   // 24,000,000 floats

#define I4_CNT   ((BB * NVOX) / 4)
#define I4_AGG   ((BB * NB + 3) / 4)
#define I4_VL    ((BB * MAXV) / 4)
#define FILL_TOTAL (I4_CNT + I4_AGG + I4_VL)

#define VALIDF (1 << 30)
#define ROWF   (MAXP * NC)               // 150 floats per feats row
#define RPB    32                         // rows per k_out block
#define NBLK_OUT ((BB * MAXV) / RPB)      // 5000

// ---------------- static device scratch (16B-aligned for vector ops) ----------
__device__ int4 g_count4[(BB * NVOX) / 4];
__device__ int4 g_agg4  [I4_AGG];
__device__ int4 g_vlist4[I4_VL];         // row -> vid (or -1)
__device__ int  g_bucket[(size_t)BB * NVOX * CAP];

#define G_COUNT ((int*)g_count4)
#define G_AGG   ((int*)g_agg4)
#define G_VLIST ((int*)g_vlist4)

// ---------------- init: counts=0, agg=0, vlist=-1 ------------------------------
__global__ void k_fill() {
    int i = blockIdx.x * blockDim.x + threadIdx.x;
    if (i < I4_CNT) { g_count4[i] = make_int4(0, 0, 0, 0); return; }
    i -= I4_CNT;
    if (i < I4_AGG) { g_agg4[i] = make_int4(0, 0, 0, 0); return; }
    i -= I4_AGG;
    if (i < I4_VL)  { g_vlist4[i] = make_int4(-1, -1, -1, -1); }
}

// ---------------- pass 1: voxelize + bucket append ----------------------------
__global__ void k_points(const float* __restrict__ pts) {
    int tid = blockIdx.x * blockDim.x + threadIdx.x;
    if (tid >= BB * NPTS) return;
    int b = tid / NPTS;
    int n = tid - b * NPTS;
    const float* p = pts + (size_t)tid * NC;
    float x = __ldg(p + 0), y = __ldg(p + 1), z = __ldg(p + 2);
    // identical float32 ops as reference: floor((p - lo) / vs)
    int ix = (int)floorf((x - 0.0f)   / 0.16f);
    int iy = (int)floorf((y + 39.68f) / 0.16f);
    int iz = (int)floorf((z + 3.0f)   / 4.0f);
    if (ix < 0 || ix >= GXX || iy < 0 || iy >= GYY || iz < 0 || iz >= GZZ) return;
    int vid = (iz * GYY + iy) * GXX + ix;
    int cell = b * NVOX + vid;
    int pos = atomicAdd(&G_COUNT[cell], 1);
    if (pos < CAP) g_bucket[(size_t)cell * CAP + pos] = n;
}

// ---------------- single-pass scan with decoupled lookback --------------------
// 212 blocks (256 thr, 16 cells/thread) fit in one wave -> spin-wait is safe.
// Output: vlist[b*MAXV + rank] = vid for the first MAXV occupied voxels.
__global__ void k_scan() {
    int blk = blockIdx.x;
    int b  = blk / NB;
    int cb = blk - b * NB;
    int t  = threadIdx.x;
    __shared__ int sh[256];

    int base = cb * CHUNK + t * 16;
    int f[16];
    int s = 0;
    #pragma unroll
    for (int q = 0; q < 16; q += 4) {
        if (base + q < NVOX) {
            int4 c4 = __ldg((const int4*)(G_COUNT + b * NVOX + base + q));
            f[q + 0] = (c4.x > 0);
            f[q + 1] = (c4.y > 0);
            f[q + 2] = (c4.z > 0);
            f[q + 3] = (c4.w > 0);
        } else {
            f[q + 0] = f[q + 1] = f[q + 2] = f[q + 3] = 0;
        }
        s += f[q + 0] + f[q + 1] + f[q + 2] + f[q + 3];
    }
    sh[t] = s;
    __syncthreads();
    #pragma unroll
    for (int off = 1; off < 256; off <<= 1) {   // Hillis–Steele inclusive
        int v = (t >= off) ? sh[t - off] : 0;
        __syncthreads();
        sh[t] += v;
        __syncthreads();
    }
    int excl  = sh[t] - s;
    int total = sh[255];

    if (t == 0) atomicExch(&G_AGG[blk], total | VALIDF);

    int partial = 0;
    for (int j = t; j < cb; j += 256) {
        int v;
        do { v = atomicAdd(&G_AGG[b * NB + j], 0); } while (!(v & VALIDF));
        partial += (v & (VALIDF - 1));
    }
    __syncthreads();
    sh[t] = partial;
    __syncthreads();
    #pragma unroll
    for (int off = 128; off > 0; off >>= 1) {
        if (t < off) sh[t] += sh[t + off];
        __syncthreads();
    }
    int r = sh[0] + excl;

    int* vl = G_VLIST + b * MAXV;
    #pragma unroll
    for (int q = 0; q < 16; q++) {
        if (f[q]) {
            if (r < MAXV) vl[r] = base + q;
            r++;
        }
    }
}

// ---------------- fused output: zero tile in gmem, overwrite real points -------
// Block owns 32 rows (19200B feats + 32 coords). 8 threads per row keep all 32
// dependent gather chains in flight concurrently.
__global__ __launch_bounds__(256) void k_out(const float* __restrict__ pts,
                                             float* __restrict__ out) {
    int r0   = blockIdx.x * RPB;
    int t    = threadIdx.x;
    int row  = r0 + (t >> 3);             // 8 threads per row
    int sub  = t & 7;
    int b    = row / MAXV;

    // issue the row's vid load first; the zero loop hides its latency
    int vid = __ldg(&G_VLIST[row]);

    // phase 1: streaming-zero this block's feats tile directly in gmem
    float4* o4 = (float4*)(out + (size_t)r0 * ROWF);
    const float4 z4 = make_float4(0.f, 0.f, 0.f, 0.f);
    #pragma unroll
    for (int i = t; i < RPB * ROWF / 4; i += 256) o4[i] = z4;

    // coords row (disjoint from feats tile, no ordering needed)
    if (sub == 0) {
        float4* co = (float4*)(out + FEATS_ELEMS) + row;
        if (vid >= 0) {
            int izc = vid / (GXX * GYY);
            int rem = vid - izc * (GXX * GYY);
            *co = make_float4((float)b, (float)izc,
                              (float)(rem / GXX), (float)(rem % GXX));
        } else {
            *co = make_float4(-1.f, -1.f, -1.f, -1.f);
        }
    }

    // zeros must land before overwrites to the same tile
    __syncthreads();

    // phase 2: overwrite real points (avg ~1.9 per row)
    if (vid < 0) return;
    int cell = b * NVOX + vid;
    int cnt  = __ldg(&G_COUNT[cell]);
    int m    = cnt < CAP ? cnt : CAP;
    const int* bk = g_bucket + (size_t)cell * CAP;

    for (int j = sub; j < m; j += 8) {
        int e = __ldg(bk + j);
        // original-order rank: #(entries < e) — bucket line is L1-hot
        int rk = 0;
        for (int q = 0; q < m; q++) rk += (__ldg(bk + q) < e);
        if (rk >= MAXP) continue;
        const float* p = pts + ((size_t)b * NPTS + e) * NC;
        float* fo = out + (size_t)row * ROWF + rk * NC;
        fo[0] = (__ldg(p + 0) - 0.0f)   / 69.12f;
        fo[1] = (__ldg(p + 1) + 39.68f) / 79.36f;
        fo[2] = (__ldg(p + 2) + 3.0f)   / 4.0f;
        fo[3] = __ldg(p + 3);
        fo[4] = __ldg(p + 4);
    }
}

// ---------------- launch ------------------------------------------------------
extern "C" void kernel_launch(void* const* d_in, const int* in_sizes, int n_in,
                              void* d_out, int out_size) {
    const float* pts = (const float*)d_in[0];
    float* out = (float*)d_out;

    k_fill  <<<(FILL_TOTAL + 255) / 256, 256>>>();
    k_points<<<(BB * NPTS + 255) / 256, 256>>>(pts);
    k_scan  <<<BB * NB, 256>>>();
    k_out   <<<NBLK_OUT, 256>>>(pts, out);
}